// round 13
// baseline (speedup 1.0000x reference)
#include <cuda_runtime.h>
#include <cuda_fp16.h>

// tcgen05 (TMEM, 5th-gen tensor core) is only available in arch-specific
// ("a") device passes. These macros exist ONLY there.
#if defined(__CUDA_ARCH_FEAT_SM103_ALL) || defined(__CUDA_ARCH_FEAT_SM100_ALL) || \
    (defined(__CUDA_ARCH_SPECIFIC__) && (__CUDA_ARCH_SPECIFIC__ == 1030 || __CUDA_ARCH_SPECIFIC__ == 1000))
#define HAS_TCGEN05 1
#else
#define HAS_TCGEN05 0
#endif

// Shapes
#define BATCH 16
#define CIN   512
#define COUT  512
#define IH    32
#define IW    32
#define OH    64
#define OW    64
#define PH    66
#define PW    66

#define LIN_SCALE  0.04419417382415922f     /* 1/sqrt(512)  */
#define CONV_SCALE 0.014731391274719844f    /* 1/sqrt(512*9)*/
#define ACT_GAIN   1.4142135623730951f
#define NEG_SLOPE  0.2f
#define EPS        1e-8f

// ---- HMMA conv smem layout (3-stage) ----
#define ASZB    38912u      // 128 rows * 152 halfs * 2B (144 + 8 pad -> 304B row)
#define XSZB    12672u      // 6 rows * 66 cols * 16 ch * 2B
#define SSZ     51584u      // ASZB + XSZB per stage
#define SMEMB_H 154752u     // 3 stages

// ---- tcgen05 conv smem layout ----
#define BSZ        32768u   // one B tile: 256 couts x 128 B (SW128)
#define HALO_OFF   98304u   // 3*BSZ
#define HALO_SZ    35904u   // 4 rows * 66 px * 136 B
#define DEMOD_OFF  170112u
#define TMEMPTR_OFF 171136u
#define MBAR_OFF   171144u
#define SMEMB_T    171264u

// ---------------- device scratch (shared between paths; per-path indexing) ----------------
// fp16 modulated padded input, 16*512*66*66 halfs (71.4 MB)
__device__ __align__(16) __half g_xm[(size_t)BATCH * 512 * PH * PW];
// fp16 scaled weights, 512*512*9
__device__ __align__(16) __half g_w[(size_t)COUT * CIN * 9];
__device__ float g_wsq[COUT * CIN];
__device__ float g_s[BATCH * CIN];
__device__ float g_demod[BATCH * COUT];

// ---------------- helpers ----------------
__device__ __forceinline__ float warp_sum(float v) {
#pragma unroll
    for (int o = 16; o > 0; o >>= 1) v += __shfl_xor_sync(0xffffffffu, v, o);
    return v;
}
__device__ __forceinline__ void cp16(unsigned d, const void* s) {
    asm volatile("cp.async.cg.shared.global [%0], [%1], 16;" ::"r"(d), "l"(s));
}
__device__ __forceinline__ void cp8(unsigned d, const void* s) {
    asm volatile("cp.async.ca.shared.global [%0], [%1], 8;" ::"r"(d), "l"(s));
}

#define MBAR_INIT(a, c) asm volatile("mbarrier.init.shared.b64 [%0], %1;" ::"r"(a), "r"(c) : "memory")
#define MBAR_INVAL(a)   asm volatile("mbarrier.inval.shared.b64 [%0];" ::"r"(a) : "memory")

__device__ __forceinline__ void mbar_wait(unsigned mbar, unsigned parity) {
    unsigned done;
    asm volatile(
        "{\n\t.reg .pred p;\n\t"
        "mbarrier.try_wait.parity.acquire.cta.shared::cta.b64 p, [%1], %2;\n\t"
        "selp.b32 %0, 1, 0, p;\n\t}"
        : "=r"(done) : "r"(mbar), "r"(parity) : "memory");
    if (!done) {
        asm volatile(
            "{\n\t.reg .pred P1;\n\t"
            "WL_%=:\n\t"
            "mbarrier.try_wait.parity.acquire.cta.shared::cta.b64 P1, [%0], %1, 0x989680;\n\t"
            "@P1 bra.uni WD_%=;\n\t"
            "bra.uni WL_%=;\n\t"
            "WD_%=:\n\t}"
            :: "r"(mbar), "r"(parity) : "memory");
    }
}

#define TCG_ST_X32(tmem_addr, r) \
    asm volatile( \
        "tcgen05.st.sync.aligned.32x32b.x32.b32 [%0], " \
        "{%1, %2, %3, %4, %5, %6, %7, %8, " \
        " %9, %10, %11, %12, %13, %14, %15, %16, " \
        " %17, %18, %19, %20, %21, %22, %23, %24, " \
        " %25, %26, %27, %28, %29, %30, %31, %32};" \
        :: "r"(tmem_addr), \
           "r"((r)[0]),  "r"((r)[1]),  "r"((r)[2]),  "r"((r)[3]), \
           "r"((r)[4]),  "r"((r)[5]),  "r"((r)[6]),  "r"((r)[7]), \
           "r"((r)[8]),  "r"((r)[9]),  "r"((r)[10]), "r"((r)[11]), \
           "r"((r)[12]), "r"((r)[13]), "r"((r)[14]), "r"((r)[15]), \
           "r"((r)[16]), "r"((r)[17]), "r"((r)[18]), "r"((r)[19]), \
           "r"((r)[20]), "r"((r)[21]), "r"((r)[22]), "r"((r)[23]), \
           "r"((r)[24]), "r"((r)[25]), "r"((r)[26]), "r"((r)[27]), \
           "r"((r)[28]), "r"((r)[29]), "r"((r)[30]), "r"((r)[31]) \
        : "memory")

#define TCG_LD_X32(r, tmem_addr) \
    asm volatile( \
        "tcgen05.ld.sync.aligned.32x32b.x32.b32 " \
        "{%0, %1, %2, %3, %4, %5, %6, %7, " \
        " %8, %9, %10, %11, %12, %13, %14, %15, " \
        " %16, %17, %18, %19, %20, %21, %22, %23, " \
        " %24, %25, %26, %27, %28, %29, %30, %31}, [%32];" \
        : "=r"((r)[0]),  "=r"((r)[1]),  "=r"((r)[2]),  "=r"((r)[3]), \
          "=r"((r)[4]),  "=r"((r)[5]),  "=r"((r)[6]),  "=r"((r)[7]), \
          "=r"((r)[8]),  "=r"((r)[9]),  "=r"((r)[10]), "=r"((r)[11]), \
          "=r"((r)[12]), "=r"((r)[13]), "=r"((r)[14]), "=r"((r)[15]), \
          "=r"((r)[16]), "=r"((r)[17]), "=r"((r)[18]), "=r"((r)[19]), \
          "=r"((r)[20]), "=r"((r)[21]), "=r"((r)[22]), "=r"((r)[23]), \
          "=r"((r)[24]), "=r"((r)[25]), "=r"((r)[26]), "=r"((r)[27]), \
          "=r"((r)[28]), "=r"((r)[29]), "=r"((r)[30]), "=r"((r)[31]) \
        : "r"(tmem_addr))

// SW128 K-major descriptor base (layout=2, Blackwell ver=1, SBO=64, LBO=1)
#define DESCBASE ((2ULL << 61) | (1ULL << 46) | (64ULL << 32) | (1ULL << 16))

// ---------------- kernel 1: style ----------------
__global__ void style_kernel(const float* __restrict__ w,
                             const float* __restrict__ lw,
                             const float* __restrict__ lb) {
    int gw = (blockIdx.x * blockDim.x + threadIdx.x) >> 5;
    int lane = threadIdx.x & 31;
    int b = gw >> 9, c = gw & 511;
    const float* wr = w + b * 512;
    const float* lr = lw + (size_t)c * 512;
    float acc = 0.f;
    for (int d = lane; d < 512; d += 32) acc += wr[d] * lr[d];
    acc = warp_sum(acc);
    if (lane == 0) g_s[gw] = acc * LIN_SCALE + lb[c];
}

// ---------------- kernel 2: weight prep (per-path layout) ----------------
__global__ void wprep_kernel(const float* __restrict__ cw) {
    int t = blockIdx.x * 256 + threadIdx.x;     // (o,i) pair
    int o = t >> 9, i = t & 511;
    const float* p = cw + (size_t)t * 9;
    float ss = 0.f;
#if HAS_TCGEN05
    int ci = i >> 6, cl = i & 63;               // [ci(8)][tap(9)][o(512)][cl(64)]
#pragma unroll
    for (int tp = 0; tp < 9; tp++) {
        float wk = p[tp] * CONV_SCALE;
        g_w[((size_t)(ci * 9 + tp) * 512 + o) * 64 + cl] = __float2half(wk);
        ss += wk * wk;
    }
#else
    int ci = i >> 4, cl = i & 15;               // [o][ci(32)][tap(9)][cl(16)]
    __half* dst = g_w + (size_t)o * 4608 + ci * 144 + cl;
#pragma unroll
    for (int tp = 0; tp < 9; tp++) {
        float wk = p[tp] * CONV_SCALE;
        dst[tp * 16] = __float2half(wk);
        ss += wk * wk;
    }
#endif
    g_wsq[t] = ss;
}

// ---------------- kernel 3: demod ----------------
__global__ void demod_kernel() {
    int gw = (blockIdx.x * blockDim.x + threadIdx.x) >> 5;
    int lane = threadIdx.x & 31;
    int b = gw >> 9, o = gw & 511;
    const float* wq = g_wsq + o * 512;
    const float* sp = g_s + b * 512;
    float acc = 0.f;
    for (int i = lane; i < 512; i += 32) {
        float sv = sp[i];
        acc += wq[i] * sv * sv;
    }
    acc = warp_sum(acc);
    if (lane == 0) g_demod[gw] = rsqrtf(acc + EPS);
}

// ---------- shared bilinear helper ----------
__device__ __forceinline__ void bilin_weights(int o, int lim, int& i0, int& i1,
                                              float& w0, float& w1) {
    int m = o >> 1;
    if (o & 1) { i0 = m; i1 = min(m + 1, lim); w0 = 0.75f; w1 = 0.25f; }
    else       { i0 = max(m - 1, 0); i1 = m;   w0 = 0.25f; w1 = 0.75f; }
}

// ---------------- kernel 4a: upsample*style, HMMA layout (fallback path) ----------------
__global__ void upmod_kernel(const float* __restrict__ x) {
    int idx = blockIdx.x * 256 + threadIdx.x;
    int c = idx % 66;
    int t2 = idx / 66;
    int r = t2 % 66; t2 /= 66;
    int cig = t2 & 31;
    int b = t2 >> 5;
    int ch0 = cig * 16;
    __half* dst = g_xm + (size_t)idx * 16;
    if (r == 0 || r == 65 || c == 0 || c == 65) {
        uint4 z = make_uint4(0u, 0u, 0u, 0u);
        ((uint4*)dst)[0] = z; ((uint4*)dst)[1] = z;
        return;
    }
    int oy = r - 1, ox = c - 1;
    int y0, y1, x0, x1; float wy0, wy1, wx0, wx1;
    bilin_weights(oy, IH - 1, y0, y1, wy0, wy1);
    bilin_weights(ox, IW - 1, x0, x1, wx0, wx1);
    const float* xb = x + ((size_t)(b * 512 + ch0)) * (IH * IW);
    const float* sb = g_s + b * 512 + ch0;
    float fv[16];
#pragma unroll
    for (int cl = 0; cl < 16; cl++) {
        const float* xp = xb + cl * (IH * IW);
        float val = wy0 * (wx0 * xp[y0 * IW + x0] + wx1 * xp[y0 * IW + x1]) +
                    wy1 * (wx0 * xp[y1 * IW + x0] + wx1 * xp[y1 * IW + x1]);
        fv[cl] = val * sb[cl];
    }
    __half2 hv[8];
#pragma unroll
    for (int c2 = 0; c2 < 8; c2++) hv[c2] = __floats2half2_rn(fv[2 * c2], fv[2 * c2 + 1]);
    ((uint4*)dst)[0] = *(uint4*)&hv[0];
    ((uint4*)dst)[1] = *(uint4*)&hv[4];
}

// ---------------- kernel 4b: upsample*style, channel-last 64 layout (tcgen05 path) ------
// R7-style thread mapping (consecutive threads share the 16-ch group, walk c)
// so warp read locality matches the proven 50us kernel; only dst differs.
__global__ void upmod_tc_kernel(const float* __restrict__ x) {
#if HAS_TCGEN05
    int idx = blockIdx.x * 256 + threadIdx.x;
    int c = idx % 66;
    int t2 = idx / 66;
    int r = t2 % 66; t2 /= 66;
    int ci16 = t2 & 31;
    int b = t2 >> 5;
    int ch0 = ci16 * 16;
    int cig = ci16 >> 2, q = ci16 & 3;
    __half* dst = g_xm + ((((size_t)(b * 8 + cig) * 66 + r) * 66 + c) * 64 + q * 16);
    if (r == 0 || r == 65 || c == 0 || c == 65) {
        uint4 z = make_uint4(0u, 0u, 0u, 0u);
        ((uint4*)dst)[0] = z; ((uint4*)dst)[1] = z;
        return;
    }
    int oy = r - 1, ox = c - 1;
    int y0, y1, x0, x1; float wy0, wy1, wx0, wx1;
    bilin_weights(oy, IH - 1, y0, y1, wy0, wy1);
    bilin_weights(ox, IW - 1, x0, x1, wx0, wx1);
    const float* xb = x + ((size_t)(b * 512 + ch0)) * (IH * IW);
    const float* sb = g_s + b * 512 + ch0;
    float fv[16];
#pragma unroll
    for (int cl = 0; cl < 16; cl++) {
        const float* xp = xb + cl * (IH * IW);
        float val = wy0 * (wx0 * xp[y0 * IW + x0] + wx1 * xp[y0 * IW + x1]) +
                    wy1 * (wx0 * xp[y1 * IW + x0] + wx1 * xp[y1 * IW + x1]);
        fv[cl] = val * sb[cl];
    }
    __half2 hv[8];
#pragma unroll
    for (int c2 = 0; c2 < 8; c2++) hv[c2] = __floats2half2_rn(fv[2 * c2], fv[2 * c2 + 1]);
    ((uint4*)dst)[0] = *(uint4*)&hv[0];
    ((uint4*)dst)[1] = *(uint4*)&hv[4];
#endif
}

// ---------------- conv (HMMA fallback) ----------------
__global__ void __launch_bounds__(256)
conv_hmma(const float* __restrict__ noise,
          const float* __restrict__ nwp,
          float* __restrict__ out) {
#if !HAS_TCGEN05
    extern __shared__ __align__(16) unsigned char smraw[];
    const unsigned sbase = (unsigned)__cvta_generic_to_shared(smraw);
    const int tid = threadIdx.x;
    const int lane = tid & 31;
    const int warp = tid >> 5;
    const int warp_m = warp >> 2;
    const int warp_n = warp & 3;
    const int b = blockIdx.z;
    const int o0 = blockIdx.y * 128;
    const int py0 = blockIdx.x * 4;

    const __half* wsrc0 = g_w + (size_t)o0 * 4608;

    auto loadA = [&](int st, int ci) {
        const __half* ws = wsrc0 + ci * 144;
        unsigned d0 = sbase + (unsigned)st * SSZ;
#pragma unroll
        for (int j2 = 0; j2 < 9; j2++) {
            int task = tid + j2 * 256;
            int row = task / 18;
            int q = task - row * 18;
            cp16(d0 + (unsigned)(row * 304 + q * 16), ws + (size_t)row * 4608 + q * 8);
        }
    };
    auto loadX = [&](int st, int ci) {
        const __half* xs = g_xm + ((size_t)(b * 32 + ci) * PH + py0) * (PW * 16);
        unsigned d0 = sbase + (unsigned)st * SSZ + ASZB;
#pragma unroll
        for (int j2 = 0; j2 < 4; j2++) {
            int task = tid + j2 * 256;
            if (task < 792) {
                int dchunk = task ^ ((task >> 3) & 1);
                cp16(d0 + (unsigned)(dchunk * 16), xs + task * 8);
            }
        }
    };

    float acc[4][8][4];
#pragma unroll
    for (int i = 0; i < 4; i++)
#pragma unroll
        for (int j = 0; j < 8; j++)
#pragma unroll
            for (int k = 0; k < 4; k++) acc[i][j][k] = 0.f;

    const unsigned arow0 = (unsigned)((warp_m * 64 + (lane & 15)) * 304 + (lane >> 4) * 16);
    const int posb4 = warp_n * PW + (lane & 7) + ((lane >> 4) << 3);
    const int matb = (lane >> 3) & 1;

    loadA(0, 0);
    loadX(0, 0);
    asm volatile("cp.async.commit_group;");

    for (int ci = 0; ci < 32; ci++) {
        int st = ci % 3;
        if (ci < 31) {
            loadA((ci + 1) % 3, ci + 1);
            loadX((ci + 1) % 3, ci + 1);
        }
        asm volatile("cp.async.commit_group;");
        asm volatile("cp.async.wait_group 1;");
        __syncthreads();
        unsigned ab = sbase + (unsigned)st * SSZ + arow0;
        unsigned bb = sbase + (unsigned)st * SSZ + ASZB;
#pragma unroll
        for (int ks = 0; ks < 9; ks++) {
            const int kh = ks / 3;
            const int kw = ks - 3 * kh;
            unsigned a[4][4];
#pragma unroll
            for (int t = 0; t < 4; t++) {
                asm volatile("ldmatrix.sync.aligned.m8n8.x4.shared.b16 {%0,%1,%2,%3}, [%4];"
                             : "=r"(a[t][0]), "=r"(a[t][1]), "=r"(a[t][2]), "=r"(a[t][3])
                             : "r"(ab + (unsigned)(t * 4864 + ks * 32)));
            }
#pragma unroll
            for (int j = 0; j < 8; j += 2) {
                int pos = posb4 + kh * PW + kw + j * 8;
                unsigned baddr = bb + (unsigned)(pos * 32 + ((matb ^ ((pos >> 2) & 1)) << 4));
                unsigned b0, b1, b2, b3;
                asm volatile("ldmatrix.sync.aligned.m8n8.x4.shared.b16 {%0,%1,%2,%3}, [%4];"
                             : "=r"(b0), "=r"(b1), "=r"(b2), "=r"(b3) : "r"(baddr));
#pragma unroll
                for (int t = 0; t < 4; t++) {
                    asm volatile(
                        "mma.sync.aligned.m16n8k16.row.col.f32.f16.f16.f32 "
                        "{%0,%1,%2,%3}, {%4,%5,%6,%7}, {%8,%9}, {%0,%1,%2,%3};"
                        : "+f"(acc[t][j][0]), "+f"(acc[t][j][1]),
                          "+f"(acc[t][j][2]), "+f"(acc[t][j][3])
                        : "r"(a[t][0]), "r"(a[t][1]), "r"(a[t][2]), "r"(a[t][3]),
                          "r"(b0), "r"(b1));
                    asm volatile(
                        "mma.sync.aligned.m16n8k16.row.col.f32.f16.f16.f32 "
                        "{%0,%1,%2,%3}, {%4,%5,%6,%7}, {%8,%9}, {%0,%1,%2,%3};"
                        : "+f"(acc[t][j + 1][0]), "+f"(acc[t][j + 1][1]),
                          "+f"(acc[t][j + 1][2]), "+f"(acc[t][j + 1][3])
                        : "r"(a[t][0]), "r"(a[t][1]), "r"(a[t][2]), "r"(a[t][3]),
                          "r"(b2), "r"(b3));
                }
            }
        }
    }

    const int g = lane >> 2, u = lane & 3;
    const int oy = py0 + warp_n;
    const float nw = nwp[0];
    const float* nrow = noise + b * (OH * OW) + oy * OW;
#pragma unroll
    for (int i = 0; i < 4; i++) {
        int o_lo = o0 + warp_m * 64 + i * 16 + g;
        float d0 = g_demod[b * 512 + o_lo];
        float d1 = g_demod[b * 512 + o_lo + 8];
#pragma unroll
        for (int j = 0; j < 8; j++) {
            int ox = j * 8 + 2 * u;
            float2 nz = *(const float2*)(nrow + ox);
            float v0 = acc[i][j][0] * d0 + nw * nz.x;
            float v1 = acc[i][j][1] * d0 + nw * nz.y;
            float v2 = acc[i][j][2] * d1 + nw * nz.x;
            float v3 = acc[i][j][3] * d1 + nw * nz.y;
            v0 = (v0 >= 0.f ? v0 : NEG_SLOPE * v0) * ACT_GAIN;
            v1 = (v1 >= 0.f ? v1 : NEG_SLOPE * v1) * ACT_GAIN;
            v2 = (v2 >= 0.f ? v2 : NEG_SLOPE * v2) * ACT_GAIN;
            v3 = (v3 >= 0.f ? v3 : NEG_SLOPE * v3) * ACT_GAIN;
            size_t base0 = (((size_t)(b * 512 + o_lo)) * OH + oy) * OW + ox;
            *(float2*)(out + base0) = make_float2(v0, v1);
            *(float2*)(out + base0 + (size_t)8 * OH * OW) = make_float2(v2, v3);
        }
    }
#endif
}

// ---------------- conv (tcgen05 TS-mode) ----------------
__global__ void __launch_bounds__(256)
conv_tc(const float* __restrict__ noise,
        const float* __restrict__ nwp,
        float* __restrict__ out) {
#if HAS_TCGEN05
    extern __shared__ __align__(1024) unsigned char smraw[];
    const unsigned sbase = (unsigned)__cvta_generic_to_shared(smraw);
    const int tid = threadIdx.x;
    const int wid = tid >> 5;
    const int b = blockIdx.z;
    const int o0 = blockIdx.y * 256;
    const int py0 = blockIdx.x * 2;

    if (tid == 0) {
#pragma unroll
        for (int i = 0; i < 4; i++) MBAR_INIT(sbase + MBAR_OFF + 8u * i, 1);
    }
    ((float*)(smraw + DEMOD_OFF))[tid] = g_demod[b * 512 + o0 + tid];
    if (wid == 0)
        asm volatile("tcgen05.alloc.cta_group::1.sync.aligned.shared::cta.b32 [%0], %1;"
                     ::"r"(sbase + TMEMPTR_OFF), "r"(512) : "memory");
    __syncthreads();
    unsigned tmem_base;
    asm volatile("ld.shared.b32 %0, [%1];" : "=r"(tmem_base) : "r"(sbase + TMEMPTR_OFF));

    auto fillB = [&](int ci, int tap, int bbuf) {
        const __half* ws = g_w + ((size_t)(ci * 9 + tap) * 512 + o0) * 64;
        unsigned d0 = sbase + (unsigned)bbuf * BSZ;
        int t0 = tid - 128;
#pragma unroll
        for (int j = 0; j < 16; j++) {
            int task = t0 + j * 128;
            int row = task >> 3, q = task & 7;
            cp16(d0 + (unsigned)(row * 128 + ((q ^ (row & 7)) << 4)), ws + row * 64 + q * 8);
        }
    };
    auto fillHalo = [&](int ci, int hb) {
        const __half* xs = g_xm + (((size_t)(b * 8 + ci) * 66 + py0) * 66) * 64;
        unsigned d0 = sbase + HALO_OFF + (unsigned)hb * HALO_SZ;
        int t0 = tid - 128;
        for (int j = 0; j < 33; j++) {
            int task = t0 + j * 128;
            if (task < 4224) {
                int p = task >> 4, u = task & 15;
                cp8(d0 + (unsigned)(p * 136 + u * 8), xs + p * 64 + u * 4);
            }
        }
    };

    if (tid >= 128) { fillB(0, 0, 0); fillHalo(0, 0); }
    asm volatile("cp.async.commit_group;");

    const unsigned idesc = (1u << 4) | (32u << 17) | (8u << 24);
    int ph[3] = {0, 0, 0};

    for (int s = 0; s < 72; s++) {
        const int buf = s % 3, ci = s / 9, tap = s % 9;
        unsigned areg[32];
        // Hoisted halo LDS: for tap>0 the halo buffer was made visible at an
        // earlier step's sync; issue the loads before the mbar wait so their
        // latency overlaps the wait/fill instead of sitting before STTM.
        if (tid < 128 && tap != 0) {
            const int m = tid;
            unsigned haddr = sbase + HALO_OFF + (unsigned)((ci & 1) * HALO_SZ) +
                (unsigned)(((((m >> 6) + tap / 3) * 66) + (m & 63) + tap % 3) * 136);
#pragma unroll
            for (int q = 0; q < 16; q++)
                asm volatile("ld.shared.v2.u32 {%0,%1}, [%2];"
                             : "=r"(areg[2 * q]), "=r"(areg[2 * q + 1]) : "r"(haddr + q * 8));
        }
        if (s >= 2) {
            int wb = (s + 1) % 3;
            mbar_wait(sbase + MBAR_OFF + 8u * wb, (unsigned)ph[wb]);
            ph[wb] ^= 1;
        }
        if (tid >= 128 && s + 1 < 72) {
            int s2 = s + 1;
            fillB(s2 / 9, s2 % 9, s2 % 3);
            if (s2 % 9 == 0) fillHalo(s2 / 9, (s2 / 9) & 1);
        }
        asm volatile("cp.async.commit_group;");
        asm volatile("cp.async.wait_group 1;");
        __syncthreads();                 // sync1: fills for step s visible to all
        if (tid < 128) {
            if (tap == 0) {
                const int m = tid;
                unsigned haddr = sbase + HALO_OFF + (unsigned)((ci & 1) * HALO_SZ) +
                    (unsigned)(((((m >> 6)) * 66) + (m & 63)) * 136);
#pragma unroll
                for (int q = 0; q < 16; q++)
                    asm volatile("ld.shared.v2.u32 {%0,%1}, [%2];"
                                 : "=r"(areg[2 * q]), "=r"(areg[2 * q + 1]) : "r"(haddr + q * 8));
            }
            TCG_ST_X32(tmem_base + 256 + buf * 32 + ((unsigned)wid << 21), areg);
            asm volatile("tcgen05.wait::st.sync.aligned;");
            asm volatile("tcgen05.fence::before_thread_sync;");
        }
        // sync2 narrowed to warps 0-4 (STTM producers + MMA issuer)
        if (tid < 160) asm volatile("bar.sync 1, 160;" ::: "memory");
        if (tid == 128) {
            asm volatile("tcgen05.fence::after_thread_sync;");
            asm volatile("fence.proxy.async.shared::cta;" ::: "memory");
            unsigned long long bd = DESCBASE |
                (((unsigned long long)((sbase + (unsigned)buf * BSZ) >> 4)) & 0x3FFFULL);
            unsigned zero = 0;
#pragma unroll
            for (int k = 0; k < 4; k++) {
                unsigned en = (s > 0 || k > 0) ? 1u : 0u;
                asm volatile(
                    "{\n\t.reg .pred p;\n\tsetp.ne.u32 p, %5, 0;\n\t"
                    "tcgen05.mma.cta_group::1.kind::f16 [%0], [%1], %2, %3, {%4, %4, %4, %4}, p;\n\t}"
                    :: "r"(tmem_base), "r"(tmem_base + 256 + buf * 32 + k * 8),
                       "l"(bd + k * 2), "r"(idesc), "r"(zero), "r"(en)
                    : "memory");
            }
            asm volatile("tcgen05.commit.cta_group::1.mbarrier::arrive::one.shared::cluster.b64 [%0];"
                         ::"r"(sbase + MBAR_OFF + 8u * buf) : "memory");
            if (s == 71)
                asm volatile("tcgen05.commit.cta_group::1.mbarrier::arrive::one.shared::cluster.b64 [%0];"
                             ::"r"(sbase + MBAR_OFF + 24u) : "memory");
        }
    }

    mbar_wait(sbase + MBAR_OFF + 24u, 0u);
    asm volatile("tcgen05.fence::after_thread_sync;");
    if (tid < 128) {
        const int m = tid;
        const int oy = py0 + (m >> 6), ox = m & 63;
        const float nz = nwp[0] * noise[b * (OH * OW) + oy * OW + ox];
        const float* dm = (const float*)(smraw + DEMOD_OFF);
        const unsigned woff = (unsigned)wid << 21;
#pragma unroll
        for (int g8 = 0; g8 < 8; g8++) {
            unsigned r[32];
            TCG_LD_X32(r, tmem_base + g8 * 32 + woff);
            asm volatile("tcgen05.wait::ld.sync.aligned;");
#pragma unroll
            for (int j = 0; j < 32; j++) {
                float v = __uint_as_float(r[j]) * dm[g8 * 32 + j] + nz;
                v = (v >= 0.f ? v : NEG_SLOPE * v) * ACT_GAIN;
                out[(((size_t)(b * 512 + o0 + g8 * 32 + j)) * OH + oy) * OW + ox] = v;
            }
        }
    }
    __syncthreads();
    if (tid == 0) {
#pragma unroll
        for (int i = 0; i < 4; i++) MBAR_INVAL(sbase + MBAR_OFF + 8u * i);
    }
    if (wid == 0) {
        asm volatile("tcgen05.relinquish_alloc_permit.cta_group::1.sync.aligned;");
        asm volatile("tcgen05.dealloc.cta_group::1.sync.aligned.b32 %0, %1;"
                     ::"r"(tmem_base), "r"(512));
    }
#endif
}

// ---------------- launcher ----------------
extern "C" void kernel_launch(void* const* d_in, const int* in_sizes, int n_in,
                              void* d_out, int out_size) {
    const float* x      = (const float*)d_in[0];
    const float* w      = (const float*)d_in[1];
    const float* noise  = (const float*)d_in[2];
    const float* lin_w  = (const float*)d_in[3];
    const float* lin_b  = (const float*)d_in[4];
    const float* conv_w = (const float*)d_in[5];
    const float* nw     = (const float*)d_in[6];
    float* out = (float*)d_out;

    cudaFuncSetAttribute(conv_hmma, cudaFuncAttributeMaxDynamicSharedMemorySize, SMEMB_H);
    cudaFuncSetAttribute(conv_tc,   cudaFuncAttributeMaxDynamicSharedMemorySize, SMEMB_T);

    // Dispatch on which conv body was compiled for the loaded arch (the
    // #if-ed-out variant is an empty kernel with few registers).
    cudaFuncAttributes fa{};
    cudaFuncGetAttributes(&fa, conv_tc);
    bool tc = fa.numRegs > 40;

    style_kernel<<<1024, 256>>>(w, lin_w, lin_b);
    wprep_kernel<<<1024, 256>>>(conv_w);
    demod_kernel<<<1024, 256>>>();
    if (tc) {
        upmod_tc_kernel<<<8712, 256>>>(x);
        conv_tc<<<dim3(32, 2, 16), 256, SMEMB_T>>>(noise, nw, out);
    } else {
        upmod_kernel<<<8712, 256>>>(x);
        conv_hmma<<<dim3(16, 4, 16), 256, SMEMB_H>>>(noise, nw, out);
    }
}

// round 14
// speedup vs baseline: 1.2282x; 1.2282x over previous
#include <cuda_runtime.h>
#include <cuda_fp16.h>

// tcgen05 (TMEM, 5th-gen tensor core) is only available in arch-specific
// ("a") device passes. These macros exist ONLY there.
#if defined(__CUDA_ARCH_FEAT_SM103_ALL) || defined(__CUDA_ARCH_FEAT_SM100_ALL) || \
    (defined(__CUDA_ARCH_SPECIFIC__) && (__CUDA_ARCH_SPECIFIC__ == 1030 || __CUDA_ARCH_SPECIFIC__ == 1000))
#define HAS_TCGEN05 1
#else
#define HAS_TCGEN05 0
#endif

// Shapes
#define BATCH 16
#define CIN   512
#define COUT  512
#define IH    32
#define IW    32
#define OH    64
#define OW    64
#define PH    66
#define PW    66

#define LIN_SCALE  0.04419417382415922f     /* 1/sqrt(512)  */
#define CONV_SCALE 0.014731391274719844f    /* 1/sqrt(512*9)*/
#define ACT_GAIN   1.4142135623730951f
#define NEG_SLOPE  0.2f
#define EPS        1e-8f

// ---- HMMA conv smem layout (3-stage) ----
#define ASZB    38912u      // 128 rows * 152 halfs * 2B (144 + 8 pad -> 304B row)
#define XSZB    12672u      // 6 rows * 66 cols * 16 ch * 2B
#define SSZ     51584u      // ASZB + XSZB per stage
#define SMEMB_H 154752u     // 3 stages

// ---- tcgen05 conv smem layout ----
#define BSZ        32768u   // one B tile: 256 couts x 128 B (SW128)
#define HALO_OFF   98304u   // 3*BSZ
#define HALO_SZ    35904u   // 4 rows * 66 px * 136 B
#define DEMOD_OFF  170112u
#define TMEMPTR_OFF 171136u
#define MBAR_OFF   171144u
#define SMEMB_T    171264u

// ---------------- device scratch (shared between paths; per-path indexing) ----------------
// fp16 modulated padded input, 16*512*66*66 halfs (71.4 MB)
__device__ __align__(16) __half g_xm[(size_t)BATCH * 512 * PH * PW];
// fp16 scaled weights, 512*512*9
__device__ __align__(16) __half g_w[(size_t)COUT * CIN * 9];
__device__ float g_wsq[COUT * CIN];
__device__ float g_s[BATCH * CIN];
__device__ float g_demod[BATCH * COUT];

// ---------------- helpers ----------------
__device__ __forceinline__ float warp_sum(float v) {
#pragma unroll
    for (int o = 16; o > 0; o >>= 1) v += __shfl_xor_sync(0xffffffffu, v, o);
    return v;
}
__device__ __forceinline__ void cp16(unsigned d, const void* s) {
    asm volatile("cp.async.cg.shared.global [%0], [%1], 16;" ::"r"(d), "l"(s));
}
__device__ __forceinline__ void cp8(unsigned d, const void* s) {
    asm volatile("cp.async.ca.shared.global [%0], [%1], 8;" ::"r"(d), "l"(s));
}

#define MBAR_INIT(a, c) asm volatile("mbarrier.init.shared.b64 [%0], %1;" ::"r"(a), "r"(c) : "memory")
#define MBAR_INVAL(a)   asm volatile("mbarrier.inval.shared.b64 [%0];" ::"r"(a) : "memory")

__device__ __forceinline__ void mbar_wait(unsigned mbar, unsigned parity) {
    unsigned done;
    asm volatile(
        "{\n\t.reg .pred p;\n\t"
        "mbarrier.try_wait.parity.acquire.cta.shared::cta.b64 p, [%1], %2;\n\t"
        "selp.b32 %0, 1, 0, p;\n\t}"
        : "=r"(done) : "r"(mbar), "r"(parity) : "memory");
    if (!done) {
        asm volatile(
            "{\n\t.reg .pred P1;\n\t"
            "WL_%=:\n\t"
            "mbarrier.try_wait.parity.acquire.cta.shared::cta.b64 P1, [%0], %1, 0x989680;\n\t"
            "@P1 bra.uni WD_%=;\n\t"
            "bra.uni WL_%=;\n\t"
            "WD_%=:\n\t}"
            :: "r"(mbar), "r"(parity) : "memory");
    }
}

#define TCG_ST_X32(tmem_addr, r) \
    asm volatile( \
        "tcgen05.st.sync.aligned.32x32b.x32.b32 [%0], " \
        "{%1, %2, %3, %4, %5, %6, %7, %8, " \
        " %9, %10, %11, %12, %13, %14, %15, %16, " \
        " %17, %18, %19, %20, %21, %22, %23, %24, " \
        " %25, %26, %27, %28, %29, %30, %31, %32};" \
        :: "r"(tmem_addr), \
           "r"((r)[0]),  "r"((r)[1]),  "r"((r)[2]),  "r"((r)[3]), \
           "r"((r)[4]),  "r"((r)[5]),  "r"((r)[6]),  "r"((r)[7]), \
           "r"((r)[8]),  "r"((r)[9]),  "r"((r)[10]), "r"((r)[11]), \
           "r"((r)[12]), "r"((r)[13]), "r"((r)[14]), "r"((r)[15]), \
           "r"((r)[16]), "r"((r)[17]), "r"((r)[18]), "r"((r)[19]), \
           "r"((r)[20]), "r"((r)[21]), "r"((r)[22]), "r"((r)[23]), \
           "r"((r)[24]), "r"((r)[25]), "r"((r)[26]), "r"((r)[27]), \
           "r"((r)[28]), "r"((r)[29]), "r"((r)[30]), "r"((r)[31]) \
        : "memory")

#define TCG_LD_X32(r, tmem_addr) \
    asm volatile( \
        "tcgen05.ld.sync.aligned.32x32b.x32.b32 " \
        "{%0, %1, %2, %3, %4, %5, %6, %7, " \
        " %8, %9, %10, %11, %12, %13, %14, %15, " \
        " %16, %17, %18, %19, %20, %21, %22, %23, " \
        " %24, %25, %26, %27, %28, %29, %30, %31}, [%32];" \
        : "=r"((r)[0]),  "=r"((r)[1]),  "=r"((r)[2]),  "=r"((r)[3]), \
          "=r"((r)[4]),  "=r"((r)[5]),  "=r"((r)[6]),  "=r"((r)[7]), \
          "=r"((r)[8]),  "=r"((r)[9]),  "=r"((r)[10]), "=r"((r)[11]), \
          "=r"((r)[12]), "=r"((r)[13]), "=r"((r)[14]), "=r"((r)[15]), \
          "=r"((r)[16]), "=r"((r)[17]), "=r"((r)[18]), "=r"((r)[19]), \
          "=r"((r)[20]), "=r"((r)[21]), "=r"((r)[22]), "=r"((r)[23]), \
          "=r"((r)[24]), "=r"((r)[25]), "=r"((r)[26]), "=r"((r)[27]), \
          "=r"((r)[28]), "=r"((r)[29]), "=r"((r)[30]), "=r"((r)[31]) \
        : "r"(tmem_addr))

// SW128 K-major descriptor base (layout=2, Blackwell ver=1, SBO=64, LBO=1)
#define DESCBASE ((2ULL << 61) | (1ULL << 46) | (64ULL << 32) | (1ULL << 16))

// ---------------- kernel 1: style ----------------
__global__ void style_kernel(const float* __restrict__ w,
                             const float* __restrict__ lw,
                             const float* __restrict__ lb) {
    int gw = (blockIdx.x * blockDim.x + threadIdx.x) >> 5;
    int lane = threadIdx.x & 31;
    int b = gw >> 9, c = gw & 511;
    const float* wr = w + b * 512;
    const float* lr = lw + (size_t)c * 512;
    float acc = 0.f;
    for (int d = lane; d < 512; d += 32) acc += wr[d] * lr[d];
    acc = warp_sum(acc);
    if (lane == 0) g_s[gw] = acc * LIN_SCALE + lb[c];
}

// ---------------- kernel 2: weight prep (per-path layout) ----------------
__global__ void wprep_kernel(const float* __restrict__ cw) {
    int t = blockIdx.x * 256 + threadIdx.x;     // (o,i) pair
    int o = t >> 9, i = t & 511;
    const float* p = cw + (size_t)t * 9;
    float ss = 0.f;
#if HAS_TCGEN05
    int ci = i >> 6, cl = i & 63;               // [ci(8)][tap(9)][o(512)][cl(64)]
#pragma unroll
    for (int tp = 0; tp < 9; tp++) {
        float wk = p[tp] * CONV_SCALE;
        g_w[((size_t)(ci * 9 + tp) * 512 + o) * 64 + cl] = __float2half(wk);
        ss += wk * wk;
    }
#else
    int ci = i >> 4, cl = i & 15;               // [o][ci(32)][tap(9)][cl(16)]
    __half* dst = g_w + (size_t)o * 4608 + ci * 144 + cl;
#pragma unroll
    for (int tp = 0; tp < 9; tp++) {
        float wk = p[tp] * CONV_SCALE;
        dst[tp * 16] = __float2half(wk);
        ss += wk * wk;
    }
#endif
    g_wsq[t] = ss;
}

// ---------------- kernel 3: demod ----------------
__global__ void demod_kernel() {
    int gw = (blockIdx.x * blockDim.x + threadIdx.x) >> 5;
    int lane = threadIdx.x & 31;
    int b = gw >> 9, o = gw & 511;
    const float* wq = g_wsq + o * 512;
    const float* sp = g_s + b * 512;
    float acc = 0.f;
    for (int i = lane; i < 512; i += 32) {
        float sv = sp[i];
        acc += wq[i] * sv * sv;
    }
    acc = warp_sum(acc);
    if (lane == 0) g_demod[gw] = rsqrtf(acc + EPS);
}

// ---------- shared bilinear helper ----------
__device__ __forceinline__ void bilin_weights(int o, int lim, int& i0, int& i1,
                                              float& w0, float& w1) {
    int m = o >> 1;
    if (o & 1) { i0 = m; i1 = min(m + 1, lim); w0 = 0.75f; w1 = 0.25f; }
    else       { i0 = max(m - 1, 0); i1 = m;   w0 = 0.25f; w1 = 0.75f; }
}

// ---------------- kernel 4a: upsample*style, HMMA layout (fallback path) ----------------
__global__ void upmod_kernel(const float* __restrict__ x) {
    int idx = blockIdx.x * 256 + threadIdx.x;
    int c = idx % 66;
    int t2 = idx / 66;
    int r = t2 % 66; t2 /= 66;
    int cig = t2 & 31;
    int b = t2 >> 5;
    int ch0 = cig * 16;
    __half* dst = g_xm + (size_t)idx * 16;
    if (r == 0 || r == 65 || c == 0 || c == 65) {
        uint4 z = make_uint4(0u, 0u, 0u, 0u);
        ((uint4*)dst)[0] = z; ((uint4*)dst)[1] = z;
        return;
    }
    int oy = r - 1, ox = c - 1;
    int y0, y1, x0, x1; float wy0, wy1, wx0, wx1;
    bilin_weights(oy, IH - 1, y0, y1, wy0, wy1);
    bilin_weights(ox, IW - 1, x0, x1, wx0, wx1);
    const float* xb = x + ((size_t)(b * 512 + ch0)) * (IH * IW);
    const float* sb = g_s + b * 512 + ch0;
    float fv[16];
#pragma unroll
    for (int cl = 0; cl < 16; cl++) {
        const float* xp = xb + cl * (IH * IW);
        float val = wy0 * (wx0 * xp[y0 * IW + x0] + wx1 * xp[y0 * IW + x1]) +
                    wy1 * (wx0 * xp[y1 * IW + x0] + wx1 * xp[y1 * IW + x1]);
        fv[cl] = val * sb[cl];
    }
    __half2 hv[8];
#pragma unroll
    for (int c2 = 0; c2 < 8; c2++) hv[c2] = __floats2half2_rn(fv[2 * c2], fv[2 * c2 + 1]);
    ((uint4*)dst)[0] = *(uint4*)&hv[0];
    ((uint4*)dst)[1] = *(uint4*)&hv[4];
}

// ---------------- kernel 4b: upsample*style, channel-last 64 layout (tcgen05 path) ------
// R7-style thread mapping (consecutive threads share the 16-ch group, walk c)
// so warp read locality matches the proven 50us kernel; only dst differs.
__global__ void upmod_tc_kernel(const float* __restrict__ x) {
#if HAS_TCGEN05
    int idx = blockIdx.x * 256 + threadIdx.x;
    int c = idx % 66;
    int t2 = idx / 66;
    int r = t2 % 66; t2 /= 66;
    int ci16 = t2 & 31;
    int b = t2 >> 5;
    int ch0 = ci16 * 16;
    int cig = ci16 >> 2, q = ci16 & 3;
    __half* dst = g_xm + ((((size_t)(b * 8 + cig) * 66 + r) * 66 + c) * 64 + q * 16);
    if (r == 0 || r == 65 || c == 0 || c == 65) {
        uint4 z = make_uint4(0u, 0u, 0u, 0u);
        ((uint4*)dst)[0] = z; ((uint4*)dst)[1] = z;
        return;
    }
    int oy = r - 1, ox = c - 1;
    int y0, y1, x0, x1; float wy0, wy1, wx0, wx1;
    bilin_weights(oy, IH - 1, y0, y1, wy0, wy1);
    bilin_weights(ox, IW - 1, x0, x1, wx0, wx1);
    const float* xb = x + ((size_t)(b * 512 + ch0)) * (IH * IW);
    const float* sb = g_s + b * 512 + ch0;
    float fv[16];
#pragma unroll
    for (int cl = 0; cl < 16; cl++) {
        const float* xp = xb + cl * (IH * IW);
        float val = wy0 * (wx0 * xp[y0 * IW + x0] + wx1 * xp[y0 * IW + x1]) +
                    wy1 * (wx0 * xp[y1 * IW + x0] + wx1 * xp[y1 * IW + x1]);
        fv[cl] = val * sb[cl];
    }
    __half2 hv[8];
#pragma unroll
    for (int c2 = 0; c2 < 8; c2++) hv[c2] = __floats2half2_rn(fv[2 * c2], fv[2 * c2 + 1]);
    ((uint4*)dst)[0] = *(uint4*)&hv[0];
    ((uint4*)dst)[1] = *(uint4*)&hv[4];
#endif
}

// ---------------- conv (HMMA fallback) ----------------
__global__ void __launch_bounds__(256)
conv_hmma(const float* __restrict__ noise,
          const float* __restrict__ nwp,
          float* __restrict__ out) {
#if !HAS_TCGEN05
    extern __shared__ __align__(16) unsigned char smraw[];
    const unsigned sbase = (unsigned)__cvta_generic_to_shared(smraw);
    const int tid = threadIdx.x;
    const int lane = tid & 31;
    const int warp = tid >> 5;
    const int warp_m = warp >> 2;
    const int warp_n = warp & 3;
    const int b = blockIdx.z;
    const int o0 = blockIdx.y * 128;
    const int py0 = blockIdx.x * 4;

    const __half* wsrc0 = g_w + (size_t)o0 * 4608;

    auto loadA = [&](int st, int ci) {
        const __half* ws = wsrc0 + ci * 144;
        unsigned d0 = sbase + (unsigned)st * SSZ;
#pragma unroll
        for (int j2 = 0; j2 < 9; j2++) {
            int task = tid + j2 * 256;
            int row = task / 18;
            int q = task - row * 18;
            cp16(d0 + (unsigned)(row * 304 + q * 16), ws + (size_t)row * 4608 + q * 8);
        }
    };
    auto loadX = [&](int st, int ci) {
        const __half* xs = g_xm + ((size_t)(b * 32 + ci) * PH + py0) * (PW * 16);
        unsigned d0 = sbase + (unsigned)st * SSZ + ASZB;
#pragma unroll
        for (int j2 = 0; j2 < 4; j2++) {
            int task = tid + j2 * 256;
            if (task < 792) {
                int dchunk = task ^ ((task >> 3) & 1);
                cp16(d0 + (unsigned)(dchunk * 16), xs + task * 8);
            }
        }
    };

    float acc[4][8][4];
#pragma unroll
    for (int i = 0; i < 4; i++)
#pragma unroll
        for (int j = 0; j < 8; j++)
#pragma unroll
            for (int k = 0; k < 4; k++) acc[i][j][k] = 0.f;

    const unsigned arow0 = (unsigned)((warp_m * 64 + (lane & 15)) * 304 + (lane >> 4) * 16);
    const int posb4 = warp_n * PW + (lane & 7) + ((lane >> 4) << 3);
    const int matb = (lane >> 3) & 1;

    loadA(0, 0);
    loadX(0, 0);
    asm volatile("cp.async.commit_group;");

    for (int ci = 0; ci < 32; ci++) {
        int st = ci % 3;
        if (ci < 31) {
            loadA((ci + 1) % 3, ci + 1);
            loadX((ci + 1) % 3, ci + 1);
        }
        asm volatile("cp.async.commit_group;");
        asm volatile("cp.async.wait_group 1;");
        __syncthreads();
        unsigned ab = sbase + (unsigned)st * SSZ + arow0;
        unsigned bb = sbase + (unsigned)st * SSZ + ASZB;
#pragma unroll
        for (int ks = 0; ks < 9; ks++) {
            const int kh = ks / 3;
            const int kw = ks - 3 * kh;
            unsigned a[4][4];
#pragma unroll
            for (int t = 0; t < 4; t++) {
                asm volatile("ldmatrix.sync.aligned.m8n8.x4.shared.b16 {%0,%1,%2,%3}, [%4];"
                             : "=r"(a[t][0]), "=r"(a[t][1]), "=r"(a[t][2]), "=r"(a[t][3])
                             : "r"(ab + (unsigned)(t * 4864 + ks * 32)));
            }
#pragma unroll
            for (int j = 0; j < 8; j += 2) {
                int pos = posb4 + kh * PW + kw + j * 8;
                unsigned baddr = bb + (unsigned)(pos * 32 + ((matb ^ ((pos >> 2) & 1)) << 4));
                unsigned b0, b1, b2, b3;
                asm volatile("ldmatrix.sync.aligned.m8n8.x4.shared.b16 {%0,%1,%2,%3}, [%4];"
                             : "=r"(b0), "=r"(b1), "=r"(b2), "=r"(b3) : "r"(baddr));
#pragma unroll
                for (int t = 0; t < 4; t++) {
                    asm volatile(
                        "mma.sync.aligned.m16n8k16.row.col.f32.f16.f16.f32 "
                        "{%0,%1,%2,%3}, {%4,%5,%6,%7}, {%8,%9}, {%0,%1,%2,%3};"
                        : "+f"(acc[t][j][0]), "+f"(acc[t][j][1]),
                          "+f"(acc[t][j][2]), "+f"(acc[t][j][3])
                        : "r"(a[t][0]), "r"(a[t][1]), "r"(a[t][2]), "r"(a[t][3]),
                          "r"(b0), "r"(b1));
                    asm volatile(
                        "mma.sync.aligned.m16n8k16.row.col.f32.f16.f16.f32 "
                        "{%0,%1,%2,%3}, {%4,%5,%6,%7}, {%8,%9}, {%0,%1,%2,%3};"
                        : "+f"(acc[t][j + 1][0]), "+f"(acc[t][j + 1][1]),
                          "+f"(acc[t][j + 1][2]), "+f"(acc[t][j + 1][3])
                        : "r"(a[t][0]), "r"(a[t][1]), "r"(a[t][2]), "r"(a[t][3]),
                          "r"(b2), "r"(b3));
                }
            }
        }
    }

    const int g = lane >> 2, u = lane & 3;
    const int oy = py0 + warp_n;
    const float nw = nwp[0];
    const float* nrow = noise + b * (OH * OW) + oy * OW;
#pragma unroll
    for (int i = 0; i < 4; i++) {
        int o_lo = o0 + warp_m * 64 + i * 16 + g;
        float d0 = g_demod[b * 512 + o_lo];
        float d1 = g_demod[b * 512 + o_lo + 8];
#pragma unroll
        for (int j = 0; j < 8; j++) {
            int ox = j * 8 + 2 * u;
            float2 nz = *(const float2*)(nrow + ox);
            float v0 = acc[i][j][0] * d0 + nw * nz.x;
            float v1 = acc[i][j][1] * d0 + nw * nz.y;
            float v2 = acc[i][j][2] * d1 + nw * nz.x;
            float v3 = acc[i][j][3] * d1 + nw * nz.y;
            v0 = (v0 >= 0.f ? v0 : NEG_SLOPE * v0) * ACT_GAIN;
            v1 = (v1 >= 0.f ? v1 : NEG_SLOPE * v1) * ACT_GAIN;
            v2 = (v2 >= 0.f ? v2 : NEG_SLOPE * v2) * ACT_GAIN;
            v3 = (v3 >= 0.f ? v3 : NEG_SLOPE * v3) * ACT_GAIN;
            size_t base0 = (((size_t)(b * 512 + o_lo)) * OH + oy) * OW + ox;
            *(float2*)(out + base0) = make_float2(v0, v1);
            *(float2*)(out + base0 + (size_t)8 * OH * OW) = make_float2(v2, v3);
        }
    }
#endif
}

// ---------------- conv (tcgen05 TS-mode; exact 477us-validated pipeline) ----------------
__global__ void __launch_bounds__(256)
conv_tc(const float* __restrict__ noise,
        const float* __restrict__ nwp,
        float* __restrict__ out) {
#if HAS_TCGEN05
    extern __shared__ __align__(1024) unsigned char smraw[];
    const unsigned sbase = (unsigned)__cvta_generic_to_shared(smraw);
    const int tid = threadIdx.x;
    const int wid = tid >> 5;
    const int b = blockIdx.z;
    const int o0 = blockIdx.y * 256;
    const int py0 = blockIdx.x * 2;

    if (tid == 0) {
#pragma unroll
        for (int i = 0; i < 4; i++) MBAR_INIT(sbase + MBAR_OFF + 8u * i, 1);
    }
    ((float*)(smraw + DEMOD_OFF))[tid] = g_demod[b * 512 + o0 + tid];
    if (wid == 0)
        asm volatile("tcgen05.alloc.cta_group::1.sync.aligned.shared::cta.b32 [%0], %1;"
                     ::"r"(sbase + TMEMPTR_OFF), "r"(512) : "memory");
    __syncthreads();
    unsigned tmem_base;
    asm volatile("ld.shared.b32 %0, [%1];" : "=r"(tmem_base) : "r"(sbase + TMEMPTR_OFF));

    auto fillB = [&](int ci, int tap, int bbuf) {
        const __half* ws = g_w + ((size_t)(ci * 9 + tap) * 512 + o0) * 64;
        unsigned d0 = sbase + (unsigned)bbuf * BSZ;
        int t0 = tid - 128;
#pragma unroll
        for (int j = 0; j < 16; j++) {
            int task = t0 + j * 128;
            int row = task >> 3, q = task & 7;
            cp16(d0 + (unsigned)(row * 128 + ((q ^ (row & 7)) << 4)), ws + row * 64 + q * 8);
        }
    };
    auto fillHalo = [&](int ci, int hb) {
        const __half* xs = g_xm + (((size_t)(b * 8 + ci) * 66 + py0) * 66) * 64;
        unsigned d0 = sbase + HALO_OFF + (unsigned)hb * HALO_SZ;
        int t0 = tid - 128;
        for (int j = 0; j < 33; j++) {
            int task = t0 + j * 128;
            if (task < 4224) {
                int p = task >> 4, u = task & 15;
                cp8(d0 + (unsigned)(p * 136 + u * 8), xs + p * 64 + u * 4);
            }
        }
    };

    if (tid >= 128) { fillB(0, 0, 0); fillHalo(0, 0); }
    asm volatile("cp.async.commit_group;");

    const unsigned idesc = (1u << 4) | (32u << 17) | (8u << 24);
    int ph[3] = {0, 0, 0};

    for (int s = 0; s < 72; s++) {
        const int buf = s % 3, ci = s / 9, tap = s % 9;
        if (s >= 2) {
            int wb = (s + 1) % 3;
            mbar_wait(sbase + MBAR_OFF + 8u * wb, (unsigned)ph[wb]);
            ph[wb] ^= 1;
        }
        if (tid >= 128 && s + 1 < 72) {
            int s2 = s + 1;
            fillB(s2 / 9, s2 % 9, s2 % 3);
            if (s2 % 9 == 0) fillHalo(s2 / 9, (s2 / 9) & 1);
        }
        asm volatile("cp.async.commit_group;");
        asm volatile("cp.async.wait_group 1;");
        __syncthreads();                 // fills for step s visible to all
        if (tid < 128) {
            const int m = tid;
            unsigned haddr = sbase + HALO_OFF + (unsigned)((ci & 1) * HALO_SZ) +
                (unsigned)(((((m >> 6) + tap / 3) * 66) + (m & 63) + tap % 3) * 136);
            unsigned r[32];
#pragma unroll
            for (int q = 0; q < 16; q++)
                asm volatile("ld.shared.v2.u32 {%0,%1}, [%2];"
                             : "=r"(r[2 * q]), "=r"(r[2 * q + 1]) : "r"(haddr + q * 8));
            TCG_ST_X32(tmem_base + 256 + buf * 32 + ((unsigned)wid << 21), r);
            asm volatile("tcgen05.wait::st.sync.aligned;");
            asm volatile("tcgen05.fence::before_thread_sync;");
        }
        __syncthreads();                 // A[buf] in TMEM
        if (tid == 128) {
            asm volatile("tcgen05.fence::after_thread_sync;");
            asm volatile("fence.proxy.async.shared::cta;" ::: "memory");
            unsigned long long bd = DESCBASE |
                (((unsigned long long)((sbase + (unsigned)buf * BSZ) >> 4)) & 0x3FFFULL);
            unsigned zero = 0;
#pragma unroll
            for (int k = 0; k < 4; k++) {
                unsigned en = (s > 0 || k > 0) ? 1u : 0u;
                asm volatile(
                    "{\n\t.reg .pred p;\n\tsetp.ne.u32 p, %5, 0;\n\t"
                    "tcgen05.mma.cta_group::1.kind::f16 [%0], [%1], %2, %3, {%4, %4, %4, %4}, p;\n\t}"
                    :: "r"(tmem_base), "r"(tmem_base + 256 + buf * 32 + k * 8),
                       "l"(bd + k * 2), "r"(idesc), "r"(zero), "r"(en)
                    : "memory");
            }
            asm volatile("tcgen05.commit.cta_group::1.mbarrier::arrive::one.shared::cluster.b64 [%0];"
                         ::"r"(sbase + MBAR_OFF + 8u * buf) : "memory");
            if (s == 71)
                asm volatile("tcgen05.commit.cta_group::1.mbarrier::arrive::one.shared::cluster.b64 [%0];"
                             ::"r"(sbase + MBAR_OFF + 24u) : "memory");
        }
    }

    mbar_wait(sbase + MBAR_OFF + 24u, 0u);
    asm volatile("tcgen05.fence::after_thread_sync;");
    if (tid < 128) {
        const int m = tid;
        const int oy = py0 + (m >> 6), ox = m & 63;
        const float nz = nwp[0] * noise[b * (OH * OW) + oy * OW + ox];
        const float* dm = (const float*)(smraw + DEMOD_OFF);
        const unsigned woff = (unsigned)wid << 21;
#pragma unroll
        for (int g8 = 0; g8 < 8; g8++) {
            unsigned r[32];
            TCG_LD_X32(r, tmem_base + g8 * 32 + woff);
            asm volatile("tcgen05.wait::ld.sync.aligned;");
#pragma unroll
            for (int j = 0; j < 32; j++) {
                float v = __uint_as_float(r[j]) * dm[g8 * 32 + j] + nz;
                v = (v >= 0.f ? v : NEG_SLOPE * v) * ACT_GAIN;
                out[(((size_t)(b * 512 + o0 + g8 * 32 + j)) * OH + oy) * OW + ox] = v;
            }
        }
    }
    __syncthreads();
    if (tid == 0) {
#pragma unroll
        for (int i = 0; i < 4; i++) MBAR_INVAL(sbase + MBAR_OFF + 8u * i);
    }
    if (wid == 0) {
        asm volatile("tcgen05.relinquish_alloc_permit.cta_group::1.sync.aligned;");
        asm volatile("tcgen05.dealloc.cta_group::1.sync.aligned.b32 %0, %1;"
                     ::"r"(tmem_base), "r"(512));
    }
#endif
}

// ---------------- launcher ----------------
extern "C" void kernel_launch(void* const* d_in, const int* in_sizes, int n_in,
                              void* d_out, int out_size) {
    const float* x      = (const float*)d_in[0];
    const float* w      = (const float*)d_in[1];
    const float* noise  = (const float*)d_in[2];
    const float* lin_w  = (const float*)d_in[3];
    const float* lin_b  = (const float*)d_in[4];
    const float* conv_w = (const float*)d_in[5];
    const float* nw     = (const float*)d_in[6];
    float* out = (float*)d_out;

    cudaFuncSetAttribute(conv_hmma, cudaFuncAttributeMaxDynamicSharedMemorySize, SMEMB_H);
    cudaFuncSetAttribute(conv_tc,   cudaFuncAttributeMaxDynamicSharedMemorySize, SMEMB_T);

    // Dispatch on which conv body was compiled for the loaded arch (the
    // #if-ed-out variant is an empty kernel with few registers).
    cudaFuncAttributes fa{};
    cudaFuncGetAttributes(&fa, conv_tc);
    bool tc = fa.numRegs > 40;

    style_kernel<<<1024, 256>>>(w, lin_w, lin_b);
    wprep_kernel<<<1024, 256>>>(conv_w);
    demod_kernel<<<1024, 256>>>();
    if (tc) {
        upmod_tc_kernel<<<8712, 256>>>(x);
        conv_tc<<<dim3(32, 2, 16), 256, SMEMB_T>>>(noise, nw, out);
    } else {
        upmod_kernel<<<8712, 256>>>(x);
        conv_hmma<<<dim3(16, 4, 16), 256, SMEMB_H>>>(noise, nw, out);
    }
}